// round 2
// baseline (speedup 1.0000x reference)
#include <cuda_runtime.h>

#define BATCH 8192
#define DIN   64
#define DMID  1024
#define DOUT  64
#define NK    4

// Scratch (allocation-free rule: __device__ globals)
__device__ float g_bufA[BATCH * DMID];   // 32 MB
__device__ float g_bufB[BATCH * DMID];   // 32 MB
__device__ int   g_perm[BATCH];
__device__ int   g_segOffset[NK + 1];
__device__ int   g_tilePrefix[NK + 1];

// ---------------------------------------------------------------------------
// Prep: detect int32 vs int64 domains, counting-sort rows by domain,
// build segment offsets + padded row-tile prefixes for branch GEMM scheduling.
// ---------------------------------------------------------------------------
__global__ void prep_kernel(const int* __restrict__ dom, int n) {
    __shared__ int cnt[NK];
    __shared__ int ofs[NK];
    __shared__ int is64flag;
    int tid = threadIdx.x;
    if (tid < NK) cnt[tid] = 0;
    if (tid == 0) is64flag = 1;
    __syncthreads();

    // int64 little-endian view => odd int32 words are high halves == 0 (values 0..3).
    for (int i = tid; i < 64; i += blockDim.x)
        if (dom[2 * i + 1] != 0) atomicAnd(&is64flag, 0);
    __syncthreads();
    const int stride = is64flag ? 2 : 1;

    for (int i = tid; i < n; i += blockDim.x)
        atomicAdd(&cnt[dom[i * stride]], 1);
    __syncthreads();

    if (tid == 0) {
        int off = 0, toff = 0;
        for (int k = 0; k < NK; k++) {
            g_segOffset[k]  = off;
            g_tilePrefix[k] = toff;
            ofs[k] = off;
            off  += cnt[k];
            toff += (cnt[k] + 127) >> 7;
        }
        g_segOffset[NK]  = off;
        g_tilePrefix[NK] = toff;
    }
    __syncthreads();

    for (int i = tid; i < n; i += blockDim.x) {
        int d = dom[i * stride];
        int p = atomicAdd(&ofs[d], 1);
        g_perm[p] = i;
    }
}

// ---------------------------------------------------------------------------
// Fused Linear(+bias)(+ReLU) GEMM:  C[M,N] = act(A[M,Kd] * W[Kd,N] + bias)
// BRANCH:  blockIdx.y maps to (domain, row segment) via g_tilePrefix; weight
//          base advances by domain * Kd * N.
// GATHER:  A row index = g_perm[row]   (branch layer 1 gathers H4)
// SCATTER: C row index = g_perm[row]   (branch layer 4 scatters output)
// TN = 128 (RN=8) for wide layers, 64 (RN=4) for the DOUT=64 layer.
// ---------------------------------------------------------------------------
template <int TN, bool RELU, bool BRANCH, bool GATHER, bool SCATTER>
__global__ __launch_bounds__(256, 2) void gemm_kernel(
    const float* __restrict__ A, const float* __restrict__ Wb,
    const float* __restrict__ biasb, float* __restrict__ C,
    int M, int Kd, int N)
{
    constexpr int TM = 128, TK = 8;
    constexpr int RM = 8, RN = TN / 16;

    __shared__ float As[TK][TM];
    __shared__ float Bs[TK][TN];
    __shared__ int   sPerm[TM];

    const int tid = threadIdx.x;
    const int tx = tid & 15;
    const int ty = tid >> 4;
    const int colBase = blockIdx.x * TN;

    int rowBase, rowEnd, dom = 0;
    if (BRANCH) {
        const int t = blockIdx.y;
        if (t >= g_tilePrefix[NK]) return;   // uniform across CTA
        int k = 0;
#pragma unroll
        for (int j = 1; j < NK; j++)
            if (t >= g_tilePrefix[j]) k = j;
        dom = k;
        rowBase = g_segOffset[k] + (t - g_tilePrefix[k]) * TM;
        rowEnd  = g_segOffset[k + 1];
    } else {
        rowBase = blockIdx.y * TM;
        rowEnd  = M;
    }

    const float* W    = Wb    + (size_t)dom * Kd * N;
    const float* bias = biasb + (size_t)dom * N;

    if (GATHER || SCATTER) {
        for (int i = tid; i < TM; i += 256) {
            int r = rowBase + i;
            sPerm[i] = (r < rowEnd) ? g_perm[r] : -1;
        }
        __syncthreads();
    }

    float acc[RM][RN];
#pragma unroll
    for (int i = 0; i < RM; i++)
#pragma unroll
        for (int j = 0; j < RN; j++) acc[i][j] = 0.f;

    const int aRowT = tid >> 1;          // 0..127
    const int aKoff = (tid & 1) * 4;     // 0 or 4

    for (int k0 = 0; k0 < Kd; k0 += TK) {
        // Load A tile (128 x 8), transposed into As[k][m]
        {
            int r = rowBase + aRowT;
            float4 v = make_float4(0.f, 0.f, 0.f, 0.f);
            if (r < rowEnd) {
                int gr = GATHER ? sPerm[aRowT] : r;
                v = *reinterpret_cast<const float4*>(A + (size_t)gr * Kd + k0 + aKoff);
            }
            As[aKoff + 0][aRowT] = v.x;
            As[aKoff + 1][aRowT] = v.y;
            As[aKoff + 2][aRowT] = v.z;
            As[aKoff + 3][aRowT] = v.w;
        }
        // Load B tile (8 x TN)
        for (int f = tid * 4; f < TK * TN; f += 1024) {
            int kr = f / TN;
            int c  = f % TN;
            float4 v = *reinterpret_cast<const float4*>(
                W + (size_t)(k0 + kr) * N + colBase + c);
            *reinterpret_cast<float4*>(&Bs[kr][c]) = v;
        }
        __syncthreads();

#pragma unroll
        for (int kk = 0; kk < TK; kk++) {
            float a[RM], b[RN];
#pragma unroll
            for (int i = 0; i < RM; i++) a[i] = As[kk][ty * RM + i];
#pragma unroll
            for (int j = 0; j < RN; j++) b[j] = Bs[kk][tx * RN + j];
#pragma unroll
            for (int i = 0; i < RM; i++)
#pragma unroll
                for (int j = 0; j < RN; j++)
                    acc[i][j] = fmaf(a[i], b[j], acc[i][j]);
        }
        __syncthreads();
    }

    // Epilogue: bias + optional ReLU, vectorized stores
    float bv[RN];
#pragma unroll
    for (int j = 0; j < RN; j++) bv[j] = bias[colBase + tx * RN + j];

#pragma unroll
    for (int i = 0; i < RM; i++) {
        const int li = ty * RM + i;
        const int r  = rowBase + li;
        if (r < rowEnd) {
            const int orow = SCATTER ? sPerm[li] : r;
            float* dst = C + (size_t)orow * N + colBase + tx * RN;
#pragma unroll
            for (int j = 0; j < RN; j += 4) {
                float4 v;
                v.x = acc[i][j + 0] + bv[j + 0];
                v.y = acc[i][j + 1] + bv[j + 1];
                v.z = acc[i][j + 2] + bv[j + 2];
                v.w = acc[i][j + 3] + bv[j + 3];
                if (RELU) {
                    v.x = fmaxf(v.x, 0.f);
                    v.y = fmaxf(v.y, 0.f);
                    v.z = fmaxf(v.z, 0.f);
                    v.w = fmaxf(v.w, 0.f);
                }
                *reinterpret_cast<float4*>(dst + j) = v;
            }
        }
    }
}

// ---------------------------------------------------------------------------
extern "C" void kernel_launch(void* const* d_in, const int* in_sizes, int n_in,
                              void* d_out, int out_size) {
    const float* X   = (const float*)d_in[0];
    const int*   dm  = (const int*)  d_in[1];
    const float* W1  = (const float*)d_in[2];
    const float* b1  = (const float*)d_in[3];
    const float* W2  = (const float*)d_in[4];
    const float* b2  = (const float*)d_in[5];
    const float* W3  = (const float*)d_in[6];
    const float* b3  = (const float*)d_in[7];
    const float* W4  = (const float*)d_in[8];
    const float* b4  = (const float*)d_in[9];
    const float* BW1 = (const float*)d_in[10];
    const float* Bb1 = (const float*)d_in[11];
    const float* BW2 = (const float*)d_in[12];
    const float* Bb2 = (const float*)d_in[13];
    const float* BW3 = (const float*)d_in[14];
    const float* Bb3 = (const float*)d_in[15];
    const float* BW4 = (const float*)d_in[16];
    const float* Bb4 = (const float*)d_in[17];
    float* out = (float*)d_out;

    float *bufA = nullptr, *bufB = nullptr;
    cudaGetSymbolAddress((void**)&bufA, g_bufA);
    cudaGetSymbolAddress((void**)&bufB, g_bufB);

    const dim3 blk(256);
    const dim3 gridMain(DMID / 128, BATCH / 128);          // (8, 64)
    const int  btiles = BATCH / 128 + NK;                  // 68 padded row tiles
    const dim3 gridBr(DMID / 128, btiles);                 // (8, 68)
    const dim3 gridBr4(DOUT / 64, btiles);                 // (1, 68)

    prep_kernel<<<1, 256>>>(dm, BATCH);

    // Shared stack: X -> A -> B -> A -> B   (H4 ends in bufB)
    gemm_kernel<128, true,  false, false, false><<<gridMain, blk>>>(X,    W1, b1, bufA, BATCH, DIN,  DMID);
    gemm_kernel<128, true,  false, false, false><<<gridMain, blk>>>(bufA, W2, b2, bufB, BATCH, DMID, DMID);
    gemm_kernel<128, true,  false, false, false><<<gridMain, blk>>>(bufB, W3, b3, bufA, BATCH, DMID, DMID);
    gemm_kernel<128, true,  false, false, false><<<gridMain, blk>>>(bufA, W4, b4, bufB, BATCH, DMID, DMID);

    // Routed branches (each row through exactly its domain's branch)
    gemm_kernel<128, true,  true,  true,  false><<<gridBr,  blk>>>(bufB, BW1, Bb1, bufA, BATCH, DMID, DMID);
    gemm_kernel<128, true,  true,  false, false><<<gridBr,  blk>>>(bufA, BW2, Bb2, bufB, BATCH, DMID, DMID);
    gemm_kernel<128, true,  true,  false, false><<<gridBr,  blk>>>(bufB, BW3, Bb3, bufA, BATCH, DMID, DMID);
    gemm_kernel<64,  false, true,  false, true ><<<gridBr4, blk>>>(bufA, BW4, Bb4, out,  BATCH, DMID, DOUT);
}

// round 4
// speedup vs baseline: 1.4087x; 1.4087x over previous
#include <cuda_runtime.h>
#include <cstdint>

#define BATCH 8192
#define DIN   64
#define DMID  1024
#define DOUT  64
#define NK    4

// Scratch (allocation-free rule: __device__ globals)
__device__ float g_bufA[BATCH * DMID];   // 32 MB
__device__ float g_bufB[BATCH * DMID];   // 32 MB
__device__ int   g_perm[BATCH];
__device__ int   g_segOffset[NK + 1];
__device__ int   g_tilePrefix[NK + 1];

// ---------------------------------------------------------------------------
// Prep: detect int32 vs int64 domains, counting-sort rows by domain,
// build segment offsets + padded row-tile prefixes for branch GEMM scheduling.
// ---------------------------------------------------------------------------
__global__ void prep_kernel(const int* __restrict__ dom, int n) {
    __shared__ int cnt[NK];
    __shared__ int ofs[NK];
    __shared__ int is64flag;
    int tid = threadIdx.x;
    if (tid < NK) cnt[tid] = 0;
    if (tid == 0) is64flag = 1;
    __syncthreads();

    // int64 little-endian view => odd int32 words (high halves) all zero.
    for (int i = tid; i < 64; i += blockDim.x)
        if (dom[2 * i + 1] != 0) atomicAnd(&is64flag, 0);
    __syncthreads();
    const int stride = is64flag ? 2 : 1;

    for (int i = tid; i < n; i += blockDim.x)
        atomicAdd(&cnt[dom[i * stride]], 1);
    __syncthreads();

    if (tid == 0) {
        int off = 0, toff = 0;
        for (int k = 0; k < NK; k++) {
            g_segOffset[k]  = off;
            g_tilePrefix[k] = toff;
            ofs[k] = off;
            off  += cnt[k];
            toff += (cnt[k] + 127) >> 7;
        }
        g_segOffset[NK]  = off;
        g_tilePrefix[NK] = toff;
    }
    __syncthreads();

    for (int i = tid; i < n; i += blockDim.x) {
        int d = dom[i * stride];
        int p = atomicAdd(&ofs[d], 1);
        g_perm[p] = i;
    }
}

// ---------------------------------------------------------------------------
// tf32 helpers
// ---------------------------------------------------------------------------
__device__ __forceinline__ uint32_t f2tf32(float x) {
    uint32_t r;
    asm("cvt.rna.tf32.f32 %0, %1;" : "=r"(r) : "f"(x));
    return r;
}

__device__ __forceinline__ void mma_tf32(float* c, const uint32_t* a, const uint32_t* b) {
    asm volatile(
        "mma.sync.aligned.m16n8k8.row.col.f32.tf32.tf32.f32 "
        "{%0,%1,%2,%3}, {%4,%5,%6,%7}, {%8,%9}, {%0,%1,%2,%3};"
        : "+f"(c[0]), "+f"(c[1]), "+f"(c[2]), "+f"(c[3])
        : "r"(a[0]), "r"(a[1]), "r"(a[2]), "r"(a[3]), "r"(b[0]), "r"(b[1]));
}

// ---------------------------------------------------------------------------
// 3xTF32 tensor-core GEMM:  C[M,N] = act(A[M,Kd] * W[Kd,N] + bias)
// CTA tile 128 x TN, K-tile 16. 8 warps.
//   TN=128: warp grid 2(m) x 4(n), warp tile 64x32 -> MF=4
//   TN=64 : warp grid 4(m) x 2(n), warp tile 32x32 -> MF=2
// A stored in SMEM [m][k] with row stride 20 (conflict-free fragment LDS)
// B stored in SMEM [k][n] with row stride TN+8 (conflict-free fragment LDS)
// Both stored twice: hi = tf32(x), lo = tf32(x - hi). 3 MMAs per fragment pair.
// ---------------------------------------------------------------------------
template <int TN, bool RELU, bool BRANCH, bool GATHER, bool SCATTER>
__global__ __launch_bounds__(256) void gemm_tc_kernel(
    const float* __restrict__ A, const float* __restrict__ Wb,
    const float* __restrict__ biasb, float* __restrict__ C,
    int M, int Kd, int N)
{
    constexpr int TM = 128, KT = 16;
    constexpr int AP = 20;        // A smem row stride (floats)
    constexpr int BP = TN + 8;    // B smem row stride (floats)
    constexpr int WMC = (TN == 128) ? 2 : 4;   // warps along M
    constexpr int WMS = TM / WMC;              // rows per warp (64 or 32)
    constexpr int MF  = WMS / 16;              // m16 fragments per warp
    constexpr int NF  = 4;                     // n8 fragments per warp (32 cols)

    __shared__ uint32_t As[2][TM * AP];   // [hi/lo][m*AP + k]
    __shared__ uint32_t Bs[2][KT * BP];   // [hi/lo][k*BP + n]
    __shared__ int      sPerm[TM];

    const int tid  = threadIdx.x;
    const int lane = tid & 31;
    const int warp = tid >> 5;
    const int wm   = warp % WMC;
    const int wn   = warp / WMC;
    const int colBase = blockIdx.x * TN;

    int rowBase, rowEnd, dom = 0;
    if (BRANCH) {
        const int t = blockIdx.y;
        if (t >= g_tilePrefix[NK]) return;   // uniform across CTA
        int k = 0;
#pragma unroll
        for (int j = 1; j < NK; j++)
            if (t >= g_tilePrefix[j]) k = j;
        dom = k;
        rowBase = g_segOffset[k] + (t - g_tilePrefix[k]) * TM;
        rowEnd  = g_segOffset[k + 1];
    } else {
        rowBase = blockIdx.y * TM;
        rowEnd  = M;
    }

    const float* W    = Wb    + (size_t)dom * Kd * N;
    const float* bias = biasb + (size_t)dom * N;

    if (GATHER || SCATTER) {
        for (int i = tid; i < TM; i += 256) {
            int r = rowBase + i;
            sPerm[i] = (r < rowEnd) ? g_perm[r] : -1;
        }
        __syncthreads();
    }

    float acc[MF][NF][4];
#pragma unroll
    for (int i = 0; i < MF; i++)
#pragma unroll
        for (int j = 0; j < NF; j++)
#pragma unroll
            for (int q = 0; q < 4; q++) acc[i][j][q] = 0.f;

    const int r0 = lane >> 2;     // 0..7
    const int kq = lane & 3;      // 0..3

    for (int k0 = 0; k0 < Kd; k0 += KT) {
        // ---- Produce A tile (128 x 16) as hi/lo tf32, layout [m][k] ----
#pragma unroll
        for (int f = tid; f < TM * KT / 4; f += 256) {
            const int m  = f >> 2;          // 4 float4 per row
            const int kk = (f & 3) * 4;
            float4 v = make_float4(0.f, 0.f, 0.f, 0.f);
            const int r = rowBase + m;
            if (r < rowEnd) {
                const int gr = GATHER ? sPerm[m] : r;
                v = *reinterpret_cast<const float4*>(A + (size_t)gr * Kd + k0 + kk);
            }
            uint32_t h0 = f2tf32(v.x), h1 = f2tf32(v.y), h2 = f2tf32(v.z), h3 = f2tf32(v.w);
            uint32_t l0 = f2tf32(v.x - __uint_as_float(h0));
            uint32_t l1 = f2tf32(v.y - __uint_as_float(h1));
            uint32_t l2 = f2tf32(v.z - __uint_as_float(h2));
            uint32_t l3 = f2tf32(v.w - __uint_as_float(h3));
            uint32_t* ph = &As[0][m * AP + kk];
            uint32_t* pl = &As[1][m * AP + kk];
            *reinterpret_cast<uint4*>(ph) = make_uint4(h0, h1, h2, h3);
            *reinterpret_cast<uint4*>(pl) = make_uint4(l0, l1, l2, l3);
        }
        // ---- Produce B tile (16 x TN), layout [k][n] ----
#pragma unroll
        for (int f = tid; f < KT * TN / 4; f += 256) {
            const int kr = f / (TN / 4);
            const int n  = (f % (TN / 4)) * 4;
            float4 v = *reinterpret_cast<const float4*>(
                W + (size_t)(k0 + kr) * N + colBase + n);
            uint32_t h0 = f2tf32(v.x), h1 = f2tf32(v.y), h2 = f2tf32(v.z), h3 = f2tf32(v.w);
            uint32_t l0 = f2tf32(v.x - __uint_as_float(h0));
            uint32_t l1 = f2tf32(v.y - __uint_as_float(h1));
            uint32_t l2 = f2tf32(v.z - __uint_as_float(h2));
            uint32_t l3 = f2tf32(v.w - __uint_as_float(h3));
            *reinterpret_cast<uint4*>(&Bs[0][kr * BP + n]) = make_uint4(h0, h1, h2, h3);
            *reinterpret_cast<uint4*>(&Bs[1][kr * BP + n]) = make_uint4(l0, l1, l2, l3);
        }
        __syncthreads();

        // ---- Consume: 2 k-steps of 8 ----
#pragma unroll
        for (int ks = 0; ks < KT; ks += 8) {
            uint32_t ah[MF][4], al[MF][4], bh[NF][2], bl[NF][2];
#pragma unroll
            for (int mf = 0; mf < MF; mf++) {
                const int mb = wm * WMS + mf * 16;
                const int i0 = (mb + r0) * AP + ks + kq;
                const int i1 = (mb + r0 + 8) * AP + ks + kq;
                ah[mf][0] = As[0][i0];     al[mf][0] = As[1][i0];
                ah[mf][1] = As[0][i1];     al[mf][1] = As[1][i1];
                ah[mf][2] = As[0][i0 + 4]; al[mf][2] = As[1][i0 + 4];
                ah[mf][3] = As[0][i1 + 4]; al[mf][3] = As[1][i1 + 4];
            }
#pragma unroll
            for (int nf = 0; nf < NF; nf++) {
                const int nb = wn * 32 + nf * 8 + r0;
                const int j0 = (ks + kq) * BP + nb;
                const int j1 = (ks + kq + 4) * BP + nb;
                bh[nf][0] = Bs[0][j0];  bl[nf][0] = Bs[1][j0];
                bh[nf][1] = Bs[0][j1];  bl[nf][1] = Bs[1][j1];
            }
#pragma unroll
            for (int mf = 0; mf < MF; mf++)
#pragma unroll
                for (int nf = 0; nf < NF; nf++) {
                    mma_tf32(acc[mf][nf], ah[mf], bh[nf]);
                    mma_tf32(acc[mf][nf], ah[mf], bl[nf]);
                    mma_tf32(acc[mf][nf], al[mf], bh[nf]);
                }
        }
        __syncthreads();
    }

    // ---- Epilogue: bias (+ReLU), float2 stores, optional scatter ----
#pragma unroll
    for (int nf = 0; nf < NF; nf++) {
        const int col = colBase + wn * 32 + nf * 8 + (lane & 3) * 2;
        const float b0 = bias[col];
        const float b1 = bias[col + 1];
#pragma unroll
        for (int mf = 0; mf < MF; mf++) {
#pragma unroll
            for (int half = 0; half < 2; half++) {
                const int li = wm * WMS + mf * 16 + (lane >> 2) + half * 8;
                const int r  = rowBase + li;
                if (r < rowEnd) {
                    const int orow = SCATTER ? sPerm[li] : r;
                    float2 v;
                    v.x = acc[mf][nf][half * 2 + 0] + b0;
                    v.y = acc[mf][nf][half * 2 + 1] + b1;
                    if (RELU) {
                        v.x = fmaxf(v.x, 0.f);
                        v.y = fmaxf(v.y, 0.f);
                    }
                    *reinterpret_cast<float2*>(C + (size_t)orow * N + col) = v;
                }
            }
        }
    }
}

// ---------------------------------------------------------------------------
extern "C" void kernel_launch(void* const* d_in, const int* in_sizes, int n_in,
                              void* d_out, int out_size) {
    const float* X   = (const float*)d_in[0];
    const int*   dm  = (const int*)  d_in[1];
    const float* W1  = (const float*)d_in[2];
    const float* b1  = (const float*)d_in[3];
    const float* W2  = (const float*)d_in[4];
    const float* b2  = (const float*)d_in[5];
    const float* W3  = (const float*)d_in[6];
    const float* b3  = (const float*)d_in[7];
    const float* W4  = (const float*)d_in[8];
    const float* b4  = (const float*)d_in[9];
    const float* BW1 = (const float*)d_in[10];
    const float* Bb1 = (const float*)d_in[11];
    const float* BW2 = (const float*)d_in[12];
    const float* Bb2 = (const float*)d_in[13];
    const float* BW3 = (const float*)d_in[14];
    const float* Bb3 = (const float*)d_in[15];
    const float* BW4 = (const float*)d_in[16];
    const float* Bb4 = (const float*)d_in[17];
    float* out = (float*)d_out;

    float *bufA = nullptr, *bufB = nullptr;
    cudaGetSymbolAddress((void**)&bufA, g_bufA);
    cudaGetSymbolAddress((void**)&bufB, g_bufB);

    const dim3 blk(256);
    const dim3 gridMain(DMID / 128, BATCH / 128);          // (8, 64)
    const int  btiles = BATCH / 128 + NK;                  // 68 padded row tiles
    const dim3 gridBr(DMID / 128, btiles);                 // (8, 68)
    const dim3 gridBr4(DOUT / 64, btiles);                 // (1, 68)

    prep_kernel<<<1, 256>>>(dm, BATCH);

    // Shared stack: X -> A -> B -> A -> B   (H4 ends in bufB)
    gemm_tc_kernel<128, true,  false, false, false><<<gridMain, blk>>>(X,    W1, b1, bufA, BATCH, DIN,  DMID);
    gemm_tc_kernel<128, true,  false, false, false><<<gridMain, blk>>>(bufA, W2, b2, bufB, BATCH, DMID, DMID);
    gemm_tc_kernel<128, true,  false, false, false><<<gridMain, blk>>>(bufB, W3, b3, bufA, BATCH, DMID, DMID);
    gemm_tc_kernel<128, true,  false, false, false><<<gridMain, blk>>>(bufA, W4, b4, bufB, BATCH, DMID, DMID);

    // Routed branches (each row through exactly its domain's branch)
    gemm_tc_kernel<128, true,  true,  true,  false><<<gridBr,  blk>>>(bufB, BW1, Bb1, bufA, BATCH, DMID, DMID);
    gemm_tc_kernel<128, true,  true,  false, false><<<gridBr,  blk>>>(bufA, BW2, Bb2, bufB, BATCH, DMID, DMID);
    gemm_tc_kernel<128, true,  true,  false, false><<<gridBr,  blk>>>(bufB, BW3, Bb3, bufA, BATCH, DMID, DMID);
    gemm_tc_kernel<64,  false, true,  false, true ><<<gridBr4, blk>>>(bufA, BW4, Bb4, out,  BATCH, DMID, DOUT);
}